// round 15
// baseline (speedup 1.0000x reference)
#include <cuda_runtime.h>
#include <cuda_fp16.h>
#include <math.h>

#define B 4
#define S 2048
#define D 512
#define H 8
#define A 64
#define HA (H*A)

// Scratch (allocation-free rule: __device__ globals) — all fp16
__device__ __half g_q[(size_t)B*H*S*A];     // Q pre-scaled by log2e/8, fp16
__device__ __half g_k[(size_t)B*H*S*A];
__device__ __half g_v[(size_t)B*H*A*S];     // V TRANSPOSED: [bh][d][s]
__device__ __half g_attn[(size_t)B*S*HA];   // attention out, fp16
__device__ __half g_xq[(size_t)B*S*D];
__device__ __half g_xk[(size_t)B*S*D];
__device__ __half g_xv[(size_t)B*S*D];
__device__ __half g_wq[(size_t)H*A*D];      // [h][a][d] (n-major)
__device__ __half g_wk[(size_t)H*A*D];
__device__ __half g_wv[(size_t)H*A*D];
__device__ __half g_wo[(size_t)D*HA];       // [d_out][ha]

// ---------------------------------------------------------------------------
// helpers
// ---------------------------------------------------------------------------
__device__ __forceinline__ void mma_f16(float c[4], const unsigned a[4],
                                        unsigned b0, unsigned b1) {
    asm volatile("mma.sync.aligned.m16n8k16.row.col.f32.f16.f16.f32 "
                 "{%0,%1,%2,%3}, {%4,%5,%6,%7}, {%8,%9}, {%0,%1,%2,%3};"
                 : "+f"(c[0]), "+f"(c[1]), "+f"(c[2]), "+f"(c[3])
                 : "r"(a[0]), "r"(a[1]), "r"(a[2]), "r"(a[3]),
                   "r"(b0), "r"(b1));
}

__device__ __forceinline__ void ldsm4(unsigned r[4], unsigned saddr) {
    asm volatile("ldmatrix.sync.aligned.m8n8.x4.shared.b16 {%0,%1,%2,%3}, [%4];"
                 : "=r"(r[0]), "=r"(r[1]), "=r"(r[2]), "=r"(r[3])
                 : "r"(saddr));
}

__device__ __forceinline__ void cpa16(__half* dst_smem, const __half* src) {
    unsigned d = (unsigned)__cvta_generic_to_shared(dst_smem);
    asm volatile("cp.async.cg.shared.global [%0], [%1], 16;" :: "r"(d), "l"(src));
}
#define CPA_COMMIT() asm volatile("cp.async.commit_group;")
#define CPA_WAIT(n)  asm volatile("cp.async.wait_group %0;" :: "n"(n))

// SWH: half-unit swizzle; rows 64 halves = 128B; 16B granule = 8 halves.
#define SWH(r, c) ((r)*64 + ((c) ^ (((r)&7) << 3)))

// ---------------------------------------------------------------------------
// Kernel 0: fused prep — fp32->fp16 convert x tensors + transpose-convert
// all weights. (unchanged from R14)
// ---------------------------------------------------------------------------
#define NX4 ((B*S*D)/4)
#define NXB (3*NX4/256)
__global__ void __launch_bounds__(256) prep_kernel(
    const float* __restrict__ q, const float* __restrict__ k,
    const float* __restrict__ v,
    const float* __restrict__ wq, const float* __restrict__ wk,
    const float* __restrict__ wv, const float* __restrict__ wo)
{
    const int bid = blockIdx.x;
    const int tid = threadIdx.x;
    if (bid < NXB) {
        int i = bid * 256 + tid;
        const float* src; __half* dst; int off;
        if      (i < 1*NX4) { src = q; dst = g_xq; off = i;         }
        else if (i < 2*NX4) { src = k; dst = g_xk; off = i - NX4;   }
        else                { src = v; dst = g_xv; off = i - 2*NX4; }
        float4 val = ((const float4*)src)[off];
        ((__half2*)dst)[2*off]     = __floats2half2_rn(val.x, val.y);
        ((__half2*)dst)[2*off + 1] = __floats2half2_rn(val.z, val.w);
        return;
    }
    __shared__ float ts[32][33];
    const int t = bid - NXB;
    const float* src; __half* dst; int M, N, tr, tc;
    if (t < 768) {
        int p = t / 256, rem = t % 256;
        int h = rem / 32, tile = rem % 32;
        tr = tile % 16; tc = tile / 16;
        M = D; N = A;
        src = (p == 0 ? wq : p == 1 ? wk : wv) + (size_t)h * D * A;
        dst = (p == 0 ? g_wq : p == 1 ? g_wk : g_wv) + (size_t)h * A * D;
    } else {
        int u = t - 768;
        tr = u % 16; tc = u / 16;
        M = HA; N = D;
        src = wo; dst = g_wo;
    }
    const int tx = tid & 31, ty = tid >> 5;
    #pragma unroll
    for (int i = ty; i < 32; i += 8)
        ts[i][tx] = src[(size_t)(tr*32 + i) * N + tc*32 + tx];
    __syncthreads();
    #pragma unroll
    for (int i = ty; i < 32; i += 8)
        dst[(size_t)(tc*32 + i) * M + tr*32 + tx] = __float2half_rn(ts[tx][i]);
}

// ---------------------------------------------------------------------------
// Kernel 1: fused QKV projection, fp16 mma (unchanged from R14 except the
// Q scale now folds log2e for the exp2-domain softmax).
// ---------------------------------------------------------------------------
__global__ void __launch_bounds__(128) proj_f16_kernel(
    const float* __restrict__ bq, const float* __restrict__ bk,
    const float* __restrict__ bv)
{
    extern __shared__ __half smh[];
    __half* Xb[2] = { smh,          smh + 8192  };
    __half* Wb[2] = { smh + 16384,  smh + 20480 };
    const unsigned smb = (unsigned)__cvta_generic_to_shared(smh);
    const unsigned Xbb[2] = { smb,             smb + 8192u*2  };
    const unsigned Wbb[2] = { smb + 16384u*2,  smb + 20480u*2 };

    const int z  = blockIdx.y;
    const int p  = z / (B*H);
    const int bh = z % (B*H);

    const __half* x = (p == 0 ? g_xq : p == 1 ? g_xk : g_xv) + (size_t)(bh / H) * S * D;
    const __half* W = (p == 0 ? g_wq : p == 1 ? g_wk : g_wv) + (size_t)(bh % H) * A * D;
    const float* bias = (p == 0 ? bq : p == 1 ? bk : bv) + (bh % H) * A;
    // Q scale: 1/sqrt(A) * log2(e)  (softmax runs in exp2 domain)
    const float scale = (p == 0) ? 0.125f * 1.44269504088896341f : 1.0f;

    const int s0   = blockIdx.x * 128;
    const int tid  = threadIdx.x;
    const int warp = tid >> 5;
    const int lane = tid & 31;
    const int grp  = lane >> 2;
    const int qr   = lane & 3;
    const int laneM = lane >> 3, laneR = lane & 7;
    const unsigned xr   = (unsigned)laneR << 3;
    const unsigned aw0  = (unsigned)(warp*32 + ((laneM&1)<<3) + laneR) * 64;
    const unsigned aw1  = aw0 + 1024;
    const unsigned acol = (unsigned)(laneM >> 1) << 3;
    const unsigned bw   = (unsigned)(((laneM>>1)<<3) + laneR) * 64;
    const unsigned bcol = (unsigned)(laneM & 1) << 3;

    float acc[2][8][4];
    #pragma unroll
    for (int g = 0; g < 2; g++)
        #pragma unroll
        for (int nt = 0; nt < 8; nt++)
            #pragma unroll
            for (int j = 0; j < 4; j++) acc[g][nt][j] = 0.0f;

    {
        #pragma unroll
        for (int u = 0; u < 8; u++) {
            int idx = (u * 128 + tid) * 8;
            int r = idx >> 6, c = idx & 63;
            cpa16(&Xb[0][SWH(r, c)], &x[(size_t)(s0 + r) * D + c]);
        }
        #pragma unroll
        for (int u = 0; u < 4; u++) {
            int idx = (u * 128 + tid) * 8;
            int r = idx >> 6, c = idx & 63;
            cpa16(&Wb[0][SWH(r, c)], &W[(size_t)r * D + c]);
        }
        CPA_COMMIT();
    }

    for (int ci = 0; ci < 8; ci++) {
        if (ci < 7) {
            int k0 = (ci + 1) * 64;
            __half* Xd = Xb[(ci + 1) & 1];
            __half* Wd = Wb[(ci + 1) & 1];
            #pragma unroll
            for (int u = 0; u < 8; u++) {
                int idx = (u * 128 + tid) * 8;
                int r = idx >> 6, c = idx & 63;
                cpa16(&Xd[SWH(r, c)], &x[(size_t)(s0 + r) * D + k0 + c]);
            }
            #pragma unroll
            for (int u = 0; u < 4; u++) {
                int idx = (u * 128 + tid) * 8;
                int r = idx >> 6, c = idx & 63;
                cpa16(&Wd[SWH(r, c)], &W[(size_t)r * D + k0 + c]);
            }
            CPA_COMMIT();
            CPA_WAIT(1);
        } else {
            CPA_WAIT(0);
        }
        __syncthreads();

        const unsigned Xs = Xbb[ci & 1];
        const unsigned Ws = Wbb[ci & 1];
        #pragma unroll
        for (int ks = 0; ks < 4; ks++) {
            const unsigned K = ks * 16;
            unsigned af0[4], af1[4];
            ldsm4(af0, Xs + ((aw0 + ((K + acol) ^ xr)) << 1));
            ldsm4(af1, Xs + ((aw1 + ((K + acol) ^ xr)) << 1));
            #pragma unroll
            for (int np = 0; np < 4; np++) {
                unsigned bf[4];
                ldsm4(bf, Ws + ((bw + np*1024u + ((K + bcol) ^ xr)) << 1));
                mma_f16(acc[0][2*np],   af0, bf[0], bf[1]);
                mma_f16(acc[1][2*np],   af1, bf[0], bf[1]);
                mma_f16(acc[0][2*np+1], af0, bf[2], bf[3]);
                mma_f16(acc[1][2*np+1], af1, bf[2], bf[3]);
            }
        }
        __syncthreads();
    }

    if (p != 2) {
        __half* out = (p == 0 ? g_q : g_k) + (size_t)bh * S * A;
        #pragma unroll
        for (int g = 0; g < 2; g++) {
            int rb = warp * 32 + g * 16 + grp;
            #pragma unroll
            for (int nt = 0; nt < 8; nt++) {
                int c = nt*8 + 2*qr;
                float b0v = bias[c], b1v = bias[c+1];
                *(__half2*)&out[(size_t)(s0 + rb) * A + c] =
                    __floats2half2_rn((acc[g][nt][0] + b0v) * scale,
                                      (acc[g][nt][1] + b1v) * scale);
                *(__half2*)&out[(size_t)(s0 + rb + 8) * A + c] =
                    __floats2half2_rn((acc[g][nt][2] + b0v) * scale,
                                      (acc[g][nt][3] + b1v) * scale);
            }
        }
    } else {
        __half* outT = g_v + (size_t)bh * A * S;
        #pragma unroll
        for (int g = 0; g < 2; g++) {
            int rb = warp * 32 + g * 16 + grp;
            #pragma unroll
            for (int nt = 0; nt < 8; nt++) {
                int c = nt*8 + 2*qr;
                float b0v = bias[c], b1v = bias[c+1];
                outT[(size_t)c     * S + s0 + rb]     = __float2half_rn(acc[g][nt][0] + b0v);
                outT[(size_t)(c+1) * S + s0 + rb]     = __float2half_rn(acc[g][nt][1] + b1v);
                outT[(size_t)c     * S + s0 + rb + 8] = __float2half_rn(acc[g][nt][2] + b0v);
                outT[(size_t)(c+1) * S + s0 + rb + 8] = __float2half_rn(acc[g][nt][3] + b1v);
            }
        }
    }
}

// ---------------------------------------------------------------------------
// Kernel 2: flash attention, fp16 mma. RESTRUCTURE vs R14:
// - K+V double-buffered, ONE commit group per block, prefetch issued after
//   the single top barrier -> 1 wait + 1 __syncthreads per iteration.
// - exp2-domain softmax (Q pre-scaled by log2e/8; exp2f everywhere).
// Smem 64KB: Qs 16K | K[2] 16K | V[2] 16K | Ps 16K -> 3 CTAs/SM.
// Causal block-skip (j<=i masked); last CTA (row S-1 fully masked -> uniform
// over ALL S keys) keeps the full loop. grid: (S/128, B*H), 128 threads.
// ---------------------------------------------------------------------------
__global__ void __launch_bounds__(128) attn_mma_kernel()
{
    extern __shared__ __half smh[];
    __half* Qs    = smh;                             // 128*64
    __half* Kb[2] = { smh + 8192,  smh + 12288 };    // 64*64 each
    __half* Vb[2] = { smh + 16384, smh + 20480 };    // 64*64 each [d][key]
    __half* Ps    = smh + 24576;                     // 128*64
    const unsigned smb = (unsigned)__cvta_generic_to_shared(smh);
    const unsigned Qsb = smb;
    const unsigned Kbb[2] = { smb + 8192u*2,  smb + 12288u*2 };
    const unsigned Vbb[2] = { smb + 16384u*2, smb + 20480u*2 };
    const unsigned Psb = smb + 24576u*2;

    const int bh = blockIdx.y;
    const int b  = bh / H;
    const int h  = bh % H;
    const int qb = blockIdx.x * 128;
    const int tid  = threadIdx.x;
    const int warp = tid >> 5;
    const int lane = tid & 31;
    const int grp  = lane >> 2;
    const int qr   = lane & 3;
    const int laneM = lane >> 3, laneR = lane & 7;
    const unsigned xr   = (unsigned)laneR << 3;
    const unsigned aw0  = (unsigned)(warp*32 + ((laneM&1)<<3) + laneR) * 64;
    const unsigned aw1  = aw0 + 1024;
    const unsigned acol = (unsigned)(laneM >> 1) << 3;
    const unsigned bw   = (unsigned)(((laneM>>1)<<3) + laneR) * 64;
    const unsigned bcol = (unsigned)(laneM & 1) << 3;

    const __half* kg  = g_k + (size_t)bh * S * 64;
    const __half* vgt = g_v + (size_t)bh * A * S;   // [d][s]
    const int j_start = (qb == S - 128) ? 0 : qb;
    const int nb = (S - j_start) >> 6;

    // ---- group 0: Q + K(0) + V(0) ----
    const __half* qg = g_q + ((size_t)bh * S + qb) * 64;
    #pragma unroll
    for (int u = 0; u < 8; u++) {
        int idx = (u * 128 + tid) * 8;
        int r = idx >> 6, c = idx & 63;
        cpa16(&Qs[SWH(r, c)], &qg[idx]);
    }
    #pragma unroll
    for (int u = 0; u < 4; u++) {
        int idx = (u * 128 + tid) * 8;
        int r = idx >> 6, c = idx & 63;
        cpa16(&Kb[0][SWH(r, c)], &kg[(size_t)j_start * 64 + idx]);
        cpa16(&Vb[0][SWH(r, c)], &vgt[(size_t)r * S + j_start + c]);
    }
    CPA_COMMIT();

    float oacc[2][8][4];
    #pragma unroll
    for (int g = 0; g < 2; g++)
        #pragma unroll
        for (int nt = 0; nt < 8; nt++)
            #pragma unroll
            for (int j = 0; j < 4; j++) oacc[g][nt][j] = 0.0f;

    float m[4], l[4];
    #pragma unroll
    for (int q = 0; q < 4; q++) { m[q] = -INFINITY; l[q] = 0.0f; }

    for (int it = 0; it < nb; it++) {
        const int j0 = j_start + (it << 6);

        // ---- single wait + single barrier per block ----
        CPA_WAIT(0);           // data for block it arrived
        __syncthreads();       // also: all warps done with buf^1 (iter it-1)

        // ---- prefetch block it+1 into the other buffer (overlaps compute)
        if (it + 1 < nb) {
            int jn = j0 + 64;
            __half* Kd = Kb[(it + 1) & 1];
            __half* Vd = Vb[(it + 1) & 1];
            #pragma unroll
            for (int u = 0; u < 4; u++) {
                int idx = (u * 128 + tid) * 8;
                int r = idx >> 6, c = idx & 63;
                cpa16(&Kd[SWH(r, c)], &kg[(size_t)jn * 64 + idx]);
                cpa16(&Vd[SWH(r, c)], &vgt[(size_t)r * S + jn + c]);
            }
            CPA_COMMIT();
        }

        const unsigned Ks = Kbb[it & 1];
        const unsigned Vs = Vbb[it & 1];

        // ---- S = Q * K^T ----
        float sacc[2][8][4];
        #pragma unroll
        for (int g = 0; g < 2; g++)
            #pragma unroll
            for (int nt = 0; nt < 8; nt++)
                #pragma unroll
                for (int j = 0; j < 4; j++) sacc[g][nt][j] = 0.0f;

        #pragma unroll
        for (int ks = 0; ks < 4; ks++) {
            const unsigned K = ks * 16;
            unsigned qa0[4], qa1[4];
            ldsm4(qa0, Qsb + ((aw0 + ((K + acol) ^ xr)) << 1));
            ldsm4(qa1, Qsb + ((aw1 + ((K + acol) ^ xr)) << 1));
            #pragma unroll
            for (int np = 0; np < 4; np++) {
                unsigned kb[4];
                ldsm4(kb, Ks + ((bw + np*1024u + ((K + bcol) ^ xr)) << 1));
                mma_f16(sacc[0][2*np],   qa0, kb[0], kb[1]);
                mma_f16(sacc[1][2*np],   qa1, kb[0], kb[1]);
                mma_f16(sacc[0][2*np+1], qa0, kb[2], kb[3]);
                mma_f16(sacc[1][2*np+1], qa1, kb[2], kb[3]);
            }
        }

        // ---- mask + online softmax (exp2 domain); P -> Ps (fp16) ----
        #pragma unroll
        for (int g = 0; g < 2; g++) {
            const int iA = qb + warp * 32 + g * 16 + grp;
            const int iB = iA + 8;
            float tmaxA = -INFINITY, tmaxB = -INFINITY;
            #pragma unroll
            for (int nt = 0; nt < 8; nt++) {
                int j = j0 + nt*8 + 2*qr;
                if (j     <= iA) sacc[g][nt][0] = -1.0e9f;
                if (j + 1 <= iA) sacc[g][nt][1] = -1.0e9f;
                if (j     <= iB) sacc[g][nt][2] = -1.0e9f;
                if (j + 1 <= iB) sacc[g][nt][3] = -1.0e9f;
                tmaxA = fmaxf(tmaxA, fmaxf(sacc[g][nt][0], sacc[g][nt][1]));
                tmaxB = fmaxf(tmaxB, fmaxf(sacc[g][nt][2], sacc[g][nt][3]));
            }
            tmaxA = fmaxf(tmaxA, __shfl_xor_sync(0xffffffffu, tmaxA, 1));
            tmaxA = fmaxf(tmaxA, __shfl_xor_sync(0xffffffffu, tmaxA, 2));
            tmaxB = fmaxf(tmaxB, __shfl_xor_sync(0xffffffffu, tmaxB, 1));
            tmaxB = fmaxf(tmaxB, __shfl_xor_sync(0xffffffffu, tmaxB, 2));

            float mnA = fmaxf(m[2*g],   tmaxA);
            float mnB = fmaxf(m[2*g+1], tmaxB);
            float crA = exp2f(m[2*g]   - mnA);   // first block: exp2(-inf)=0
            float crB = exp2f(m[2*g+1] - mnB);
            l[2*g]   *= crA; l[2*g+1] *= crB;
            m[2*g]    = mnA; m[2*g+1]  = mnB;
            #pragma unroll
            for (int nt = 0; nt < 8; nt++) {
                oacc[g][nt][0] *= crA; oacc[g][nt][1] *= crA;
                oacc[g][nt][2] *= crB; oacc[g][nt][3] *= crB;
            }

            float lsA = 0.0f, lsB = 0.0f;
            int rb = warp * 32 + g * 16 + grp;
            #pragma unroll
            for (int nt = 0; nt < 8; nt++) {
                float p0 = exp2f(sacc[g][nt][0] - mnA);
                float p1 = exp2f(sacc[g][nt][1] - mnA);
                float p2 = exp2f(sacc[g][nt][2] - mnB);
                float p3 = exp2f(sacc[g][nt][3] - mnB);
                lsA += p0 + p1; lsB += p2 + p3;
                int c = nt*8 + 2*qr;
                *(__half2*)&Ps[SWH(rb, c)]     = __floats2half2_rn(p0, p1);
                *(__half2*)&Ps[SWH(rb + 8, c)] = __floats2half2_rn(p2, p3);
            }
            l[2*g] += lsA; l[2*g+1] += lsB;
        }
        __syncwarp();   // P rows are warp-private; order stores before loads

        // ---- O += P * V ----
        #pragma unroll
        for (int ks = 0; ks < 4; ks++) {
            const unsigned K = ks * 16;
            unsigned pa0[4], pa1[4];
            ldsm4(pa0, Psb + ((aw0 + ((K + acol) ^ xr)) << 1));
            ldsm4(pa1, Psb + ((aw1 + ((K + acol) ^ xr)) << 1));
            #pragma unroll
            for (int np = 0; np < 4; np++) {
                unsigned vb[4];
                ldsm4(vb, Vs + ((bw + np*1024u + ((K + bcol) ^ xr)) << 1));
                mma_f16(oacc[0][2*np],   pa0, vb[0], vb[1]);
                mma_f16(oacc[1][2*np],   pa1, vb[0], vb[1]);
                mma_f16(oacc[0][2*np+1], pa0, vb[2], vb[3]);
                mma_f16(oacc[1][2*np+1], pa1, vb[2], vb[3]);
            }
        }
        // no end barrier: next iteration's top barrier covers buffer reuse
    }

    // ---- quad-reduce softmax denominators ----
    #pragma unroll
    for (int q = 0; q < 4; q++) {
        l[q] += __shfl_xor_sync(0xffffffffu, l[q], 1);
        l[q] += __shfl_xor_sync(0xffffffffu, l[q], 2);
    }

    // ---- epilogue: normalize, fp16, head-concat layout ----
    #pragma unroll
    for (int g = 0; g < 2; g++) {
        const int iA = qb + warp * 32 + g * 16 + grp;
        const float invA = 1.0f / l[2*g];
        const float invB = 1.0f / l[2*g+1];
        __half* obA = g_attn + ((size_t)b * S + iA) * HA + h * A;
        __half* obB = g_attn + ((size_t)b * S + iA + 8) * HA + h * A;
        #pragma unroll
        for (int nt = 0; nt < 8; nt++) {
            int c = nt*8 + 2*qr;
            *(__half2*)&obA[c] = __floats2half2_rn(oacc[g][nt][0] * invA,
                                                   oacc[g][nt][1] * invA);
            *(__half2*)&obB[c] = __floats2half2_rn(oacc[g][nt][2] * invB,
                                                   oacc[g][nt][3] * invB);
        }
    }
}

// ---------------------------------------------------------------------------
// Kernel 3: output projection, fp16 mma (unchanged from R14 — validated).
// ---------------------------------------------------------------------------
__global__ void __launch_bounds__(128) out_proj_f16_kernel(
    const float* __restrict__ bo, float* __restrict__ out)
{
    extern __shared__ __half smh[];
    __half* Xb[2] = { smh,          smh + 8192  };
    __half* Wb[2] = { smh + 16384,  smh + 20480 };
    const unsigned smb = (unsigned)__cvta_generic_to_shared(smh);
    const unsigned Xbb[2] = { smb,             smb + 8192u*2  };
    const unsigned Wbb[2] = { smb + 16384u*2,  smb + 20480u*2 };

    const int n0 = blockIdx.x * 64;
    const int s0 = blockIdx.y * 128;
    const int tid  = threadIdx.x;
    const int warp = tid >> 5;
    const int lane = tid & 31;
    const int grp  = lane >> 2;
    const int qr   = lane & 3;
    const int laneM = lane >> 3, laneR = lane & 7;
    const unsigned xr   = (unsigned)laneR << 3;
    const unsigned aw0  = (unsigned)(warp*32 + ((laneM&1)<<3) + laneR) * 64;
    const unsigned aw1  = aw0 + 1024;
    const unsigned acol = (unsigned)(laneM >> 1) << 3;
    const unsigned bw   = (unsigned)(((laneM>>1)<<3) + laneR) * 64;
    const unsigned bcol = (unsigned)(laneM & 1) << 3;

    float acc[2][8][4];
    #pragma unroll
    for (int g = 0; g < 2; g++)
        #pragma unroll
        for (int nt = 0; nt < 8; nt++)
            #pragma unroll
            for (int j = 0; j < 4; j++) acc[g][nt][j] = 0.0f;

    {
        #pragma unroll
        for (int u = 0; u < 8; u++) {
            int idx = (u * 128 + tid) * 8;
            int r = idx >> 6, c = idx & 63;
            cpa16(&Xb[0][SWH(r, c)], &g_attn[(size_t)(s0 + r) * HA + c]);
        }
        #pragma unroll
        for (int u = 0; u < 4; u++) {
            int idx = (u * 128 + tid) * 8;
            int r = idx >> 6, c = idx & 63;
            cpa16(&Wb[0][SWH(r, c)], &g_wo[(size_t)(n0 + r) * HA + c]);
        }
        CPA_COMMIT();
    }

    for (int ci = 0; ci < 8; ci++) {
        if (ci < 7) {
            int k0 = (ci + 1) * 64;
            __half* Xd = Xb[(ci + 1) & 1];
            __half* Wd = Wb[(ci + 1) & 1];
            #pragma unroll
            for (int u = 0; u < 8; u++) {
                int idx = (u * 128 + tid) * 8;
                int r = idx >> 6, c = idx & 63;
                cpa16(&Xd[SWH(r, c)], &g_attn[(size_t)(s0 + r) * HA + k0 + c]);
            }
            #pragma unroll
            for (int u = 0; u < 4; u++) {
                int idx = (u * 128 + tid) * 8;
                int r = idx >> 6, c = idx & 63;
                cpa16(&Wd[SWH(r, c)], &g_wo[(size_t)(n0 + r) * HA + k0 + c]);
            }
            CPA_COMMIT();
            CPA_WAIT(1);
        } else {
            CPA_WAIT(0);
        }
        __syncthreads();

        const unsigned Xs = Xbb[ci & 1];
        const unsigned Ws = Wbb[ci & 1];
        #pragma unroll
        for (int ks = 0; ks < 4; ks++) {
            const unsigned K = ks * 16;
            unsigned af0[4], af1[4];
            ldsm4(af0, Xs + ((aw0 + ((K + acol) ^ xr)) << 1));
            ldsm4(af1, Xs + ((aw1 + ((K + acol) ^ xr)) << 1));
            #pragma unroll
            for (int np = 0; np < 4; np++) {
                unsigned bf[4];
                ldsm4(bf, Ws + ((bw + np*1024u + ((K + bcol) ^ xr)) << 1));
                mma_f16(acc[0][2*np],   af0, bf[0], bf[1]);
                mma_f16(acc[1][2*np],   af1, bf[0], bf[1]);
                mma_f16(acc[0][2*np+1], af0, bf[2], bf[3]);
                mma_f16(acc[1][2*np+1], af1, bf[2], bf[3]);
            }
        }
        __syncthreads();
    }

    #pragma unroll
    for (int g = 0; g < 2; g++) {
        int rb = warp * 32 + g * 16 + grp;
        #pragma unroll
        for (int nt = 0; nt < 8; nt++) {
            int c = nt*8 + 2*qr;
            float2 bv2 = make_float2(bo[n0 + c], bo[n0 + c + 1]);
            *(float2*)&out[(size_t)(s0 + rb) * D + n0 + c] =
                make_float2(acc[g][nt][0] + bv2.x, acc[g][nt][1] + bv2.y);
            *(float2*)&out[(size_t)(s0 + rb + 8) * D + n0 + c] =
                make_float2(acc[g][nt][2] + bv2.x, acc[g][nt][3] + bv2.y);
        }
    }
}

// ---------------------------------------------------------------------------
extern "C" void kernel_launch(void* const* d_in, const int* in_sizes, int n_in,
                              void* d_out, int out_size)
{
    const float* query = (const float*)d_in[0];
    const float* key   = (const float*)d_in[1];
    const float* value = (const float*)d_in[2];
    const float* Wq    = (const float*)d_in[3];
    const float* bq    = (const float*)d_in[4];
    const float* Wk    = (const float*)d_in[5];
    const float* bk    = (const float*)d_in[6];
    const float* Wv    = (const float*)d_in[7];
    const float* bv    = (const float*)d_in[8];
    const float* Wo    = (const float*)d_in[9];
    const float* bo    = (const float*)d_in[10];
    float* out = (float*)d_out;

    (void)in_sizes; (void)n_in; (void)out_size;

    prep_kernel<<<NXB + 1024, 256>>>(query, key, value, Wq, Wk, Wv, Wo);

    // dynamic smem attribute sets: idempotent, capture-safe, no allocation
    static const int SMEM48 = 24576 * (int)sizeof(__half);   // 49152 B
    static const int SMEM64 = 32768 * (int)sizeof(__half);   // 65536 B
    cudaFuncSetAttribute(proj_f16_kernel,
                         cudaFuncAttributeMaxDynamicSharedMemorySize, SMEM48);
    cudaFuncSetAttribute(attn_mma_kernel,
                         cudaFuncAttributeMaxDynamicSharedMemorySize, SMEM64);
    cudaFuncSetAttribute(out_proj_f16_kernel,
                         cudaFuncAttributeMaxDynamicSharedMemorySize, SMEM48);

    proj_f16_kernel<<<dim3(S / 128, 3 * B * H), 128, SMEM48>>>(bq, bk, bv);

    attn_mma_kernel<<<dim3(S / 128, B * H), 128, SMEM64>>>();

    out_proj_f16_kernel<<<dim3(D / 64, (B * S) / 128), 128, SMEM48>>>(bo, out);
}

// round 16
// speedup vs baseline: 1.0129x; 1.0129x over previous
#include <cuda_runtime.h>
#include <cuda_fp16.h>
#include <math.h>

#define B 4
#define S 2048
#define D 512
#define H 8
#define A 64
#define HA (H*A)

// Scratch (allocation-free rule: __device__ globals) — all fp16
__device__ __half g_q[(size_t)B*H*S*A];     // Q pre-scaled by 1/8, fp16
__device__ __half g_k[(size_t)B*H*S*A];
__device__ __half g_v[(size_t)B*H*A*S];     // V TRANSPOSED: [bh][d][s]
__device__ __half g_attn[(size_t)B*S*HA];   // attention out, fp16
__device__ __half g_xq[(size_t)B*S*D];
__device__ __half g_xk[(size_t)B*S*D];
__device__ __half g_xv[(size_t)B*S*D];
__device__ __half g_wq[(size_t)H*A*D];      // [h][a][d] (n-major)
__device__ __half g_wk[(size_t)H*A*D];
__device__ __half g_wv[(size_t)H*A*D];
__device__ __half g_wo[(size_t)D*HA];       // [d_out][ha]

// ---------------------------------------------------------------------------
// helpers
// ---------------------------------------------------------------------------
__device__ __forceinline__ void mma_f16(float c[4], const unsigned a[4],
                                        unsigned b0, unsigned b1) {
    asm volatile("mma.sync.aligned.m16n8k16.row.col.f32.f16.f16.f32 "
                 "{%0,%1,%2,%3}, {%4,%5,%6,%7}, {%8,%9}, {%0,%1,%2,%3};"
                 : "+f"(c[0]), "+f"(c[1]), "+f"(c[2]), "+f"(c[3])
                 : "r"(a[0]), "r"(a[1]), "r"(a[2]), "r"(a[3]),
                   "r"(b0), "r"(b1));
}

__device__ __forceinline__ void ldsm4(unsigned r[4], unsigned saddr) {
    asm volatile("ldmatrix.sync.aligned.m8n8.x4.shared.b16 {%0,%1,%2,%3}, [%4];"
                 : "=r"(r[0]), "=r"(r[1]), "=r"(r[2]), "=r"(r[3])
                 : "r"(saddr));
}

__device__ __forceinline__ void cpa16(__half* dst_smem, const __half* src) {
    unsigned d = (unsigned)__cvta_generic_to_shared(dst_smem);
    asm volatile("cp.async.cg.shared.global [%0], [%1], 16;" :: "r"(d), "l"(src));
}
#define CPA_COMMIT() asm volatile("cp.async.commit_group;")
#define CPA_WAIT(n)  asm volatile("cp.async.wait_group %0;" :: "n"(n))

// SWH: half-unit swizzle. Rows are 64 halves = 128B; 16B granule = 8 halves.
#define SWH(r, c) ((r)*64 + ((c) ^ (((r)&7) << 3)))

// ---------------------------------------------------------------------------
// Kernel 0: fused prep — fp32->fp16 convert x tensors + transpose-convert
// all weights. (R14, validated)
// ---------------------------------------------------------------------------
#define NX4 ((B*S*D)/4)
#define NXB (3*NX4/256)
__global__ void __launch_bounds__(256) prep_kernel(
    const float* __restrict__ q, const float* __restrict__ k,
    const float* __restrict__ v,
    const float* __restrict__ wq, const float* __restrict__ wk,
    const float* __restrict__ wv, const float* __restrict__ wo)
{
    const int bid = blockIdx.x;
    const int tid = threadIdx.x;
    if (bid < NXB) {
        int i = bid * 256 + tid;
        const float* src; __half* dst; int off;
        if      (i < 1*NX4) { src = q; dst = g_xq; off = i;         }
        else if (i < 2*NX4) { src = k; dst = g_xk; off = i - NX4;   }
        else                { src = v; dst = g_xv; off = i - 2*NX4; }
        float4 val = ((const float4*)src)[off];
        ((__half2*)dst)[2*off]     = __floats2half2_rn(val.x, val.y);
        ((__half2*)dst)[2*off + 1] = __floats2half2_rn(val.z, val.w);
        return;
    }
    __shared__ float ts[32][33];
    const int t = bid - NXB;
    const float* src; __half* dst; int M, N, tr, tc;
    if (t < 768) {
        int p = t / 256, rem = t % 256;
        int h = rem / 32, tile = rem % 32;
        tr = tile % 16; tc = tile / 16;
        M = D; N = A;
        src = (p == 0 ? wq : p == 1 ? wk : wv) + (size_t)h * D * A;
        dst = (p == 0 ? g_wq : p == 1 ? g_wk : g_wv) + (size_t)h * A * D;
    } else {
        int u = t - 768;
        tr = u % 16; tc = u / 16;
        M = HA; N = D;
        src = wo; dst = g_wo;
    }
    const int tx = tid & 31, ty = tid >> 5;
    #pragma unroll
    for (int i = ty; i < 32; i += 8)
        ts[i][tx] = src[(size_t)(tr*32 + i) * N + tc*32 + tx];
    __syncthreads();
    #pragma unroll
    for (int i = ty; i < 32; i += 8)
        dst[(size_t)(tc*32 + i) * M + tr*32 + tx] = __float2half_rn(ts[tx][i]);
}

// ---------------------------------------------------------------------------
// Kernel 1: fused QKV projection, fp16 mma. (R14, validated)
// ---------------------------------------------------------------------------
__global__ void __launch_bounds__(128) proj_f16_kernel(
    const float* __restrict__ bq, const float* __restrict__ bk,
    const float* __restrict__ bv)
{
    extern __shared__ __half smh[];
    __half* Xb[2] = { smh,          smh + 8192  };
    __half* Wb[2] = { smh + 16384,  smh + 20480 };
    const unsigned smb = (unsigned)__cvta_generic_to_shared(smh);
    const unsigned Xbb[2] = { smb,             smb + 8192u*2  };
    const unsigned Wbb[2] = { smb + 16384u*2,  smb + 20480u*2 };

    const int z  = blockIdx.y;
    const int p  = z / (B*H);
    const int bh = z % (B*H);

    const __half* x = (p == 0 ? g_xq : p == 1 ? g_xk : g_xv) + (size_t)(bh / H) * S * D;
    const __half* W = (p == 0 ? g_wq : p == 1 ? g_wk : g_wv) + (size_t)(bh % H) * A * D;
    const float* bias = (p == 0 ? bq : p == 1 ? bk : bv) + (bh % H) * A;
    const float scale = (p == 0) ? 0.125f : 1.0f;

    const int s0   = blockIdx.x * 128;
    const int tid  = threadIdx.x;
    const int warp = tid >> 5;
    const int lane = tid & 31;
    const int grp  = lane >> 2;
    const int qr   = lane & 3;
    const int laneM = lane >> 3, laneR = lane & 7;
    const unsigned xr   = (unsigned)laneR << 3;
    const unsigned aw0  = (unsigned)(warp*32 + ((laneM&1)<<3) + laneR) * 64;
    const unsigned aw1  = aw0 + 1024;
    const unsigned acol = (unsigned)(laneM >> 1) << 3;
    const unsigned bw   = (unsigned)(((laneM>>1)<<3) + laneR) * 64;
    const unsigned bcol = (unsigned)(laneM & 1) << 3;

    float acc[2][8][4];
    #pragma unroll
    for (int g = 0; g < 2; g++)
        #pragma unroll
        for (int nt = 0; nt < 8; nt++)
            #pragma unroll
            for (int j = 0; j < 4; j++) acc[g][nt][j] = 0.0f;

    {
        #pragma unroll
        for (int u = 0; u < 8; u++) {
            int idx = (u * 128 + tid) * 8;
            int r = idx >> 6, c = idx & 63;
            cpa16(&Xb[0][SWH(r, c)], &x[(size_t)(s0 + r) * D + c]);
        }
        #pragma unroll
        for (int u = 0; u < 4; u++) {
            int idx = (u * 128 + tid) * 8;
            int r = idx >> 6, c = idx & 63;
            cpa16(&Wb[0][SWH(r, c)], &W[(size_t)r * D + c]);
        }
        CPA_COMMIT();
    }

    for (int ci = 0; ci < 8; ci++) {
        if (ci < 7) {
            int k0 = (ci + 1) * 64;
            __half* Xd = Xb[(ci + 1) & 1];
            __half* Wd = Wb[(ci + 1) & 1];
            #pragma unroll
            for (int u = 0; u < 8; u++) {
                int idx = (u * 128 + tid) * 8;
                int r = idx >> 6, c = idx & 63;
                cpa16(&Xd[SWH(r, c)], &x[(size_t)(s0 + r) * D + k0 + c]);
            }
            #pragma unroll
            for (int u = 0; u < 4; u++) {
                int idx = (u * 128 + tid) * 8;
                int r = idx >> 6, c = idx & 63;
                cpa16(&Wd[SWH(r, c)], &W[(size_t)r * D + k0 + c]);
            }
            CPA_COMMIT();
            CPA_WAIT(1);
        } else {
            CPA_WAIT(0);
        }
        __syncthreads();

        const unsigned Xs = Xbb[ci & 1];
        const unsigned Ws = Wbb[ci & 1];
        #pragma unroll
        for (int ks = 0; ks < 4; ks++) {
            const unsigned K = ks * 16;
            unsigned af0[4], af1[4];
            ldsm4(af0, Xs + ((aw0 + ((K + acol) ^ xr)) << 1));
            ldsm4(af1, Xs + ((aw1 + ((K + acol) ^ xr)) << 1));
            #pragma unroll
            for (int np = 0; np < 4; np++) {
                unsigned bf[4];
                ldsm4(bf, Ws + ((bw + np*1024u + ((K + bcol) ^ xr)) << 1));
                mma_f16(acc[0][2*np],   af0, bf[0], bf[1]);
                mma_f16(acc[1][2*np],   af1, bf[0], bf[1]);
                mma_f16(acc[0][2*np+1], af0, bf[2], bf[3]);
                mma_f16(acc[1][2*np+1], af1, bf[2], bf[3]);
            }
        }
        __syncthreads();
    }

    if (p != 2) {
        __half* out = (p == 0 ? g_q : g_k) + (size_t)bh * S * A;
        #pragma unroll
        for (int g = 0; g < 2; g++) {
            int rb = warp * 32 + g * 16 + grp;
            #pragma unroll
            for (int nt = 0; nt < 8; nt++) {
                int c = nt*8 + 2*qr;
                float b0v = bias[c], b1v = bias[c+1];
                *(__half2*)&out[(size_t)(s0 + rb) * A + c] =
                    __floats2half2_rn((acc[g][nt][0] + b0v) * scale,
                                      (acc[g][nt][1] + b1v) * scale);
                *(__half2*)&out[(size_t)(s0 + rb + 8) * A + c] =
                    __floats2half2_rn((acc[g][nt][2] + b0v) * scale,
                                      (acc[g][nt][3] + b1v) * scale);
            }
        }
    } else {
        __half* outT = g_v + (size_t)bh * A * S;
        #pragma unroll
        for (int g = 0; g < 2; g++) {
            int rb = warp * 32 + g * 16 + grp;
            #pragma unroll
            for (int nt = 0; nt < 8; nt++) {
                int c = nt*8 + 2*qr;
                float b0v = bias[c], b1v = bias[c+1];
                outT[(size_t)c     * S + s0 + rb]     = __float2half_rn(acc[g][nt][0] + b0v);
                outT[(size_t)(c+1) * S + s0 + rb]     = __float2half_rn(acc[g][nt][1] + b1v);
                outT[(size_t)c     * S + s0 + rb + 8] = __float2half_rn(acc[g][nt][2] + b0v);
                outT[(size_t)(c+1) * S + s0 + rb + 8] = __float2half_rn(acc[g][nt][3] + b1v);
            }
        }
    }
}

// ---------------------------------------------------------------------------
// Kernel 2: flash attention, fp16 mma — EXACT R14 kernel (validated 182.1)
// with ONE change: REVERSED CTA->tile mapping so the longest-running tiles
// (high qb: more unmasked key blocks; and the last tile's full loop) launch
// in wave 1 and short tiles backfill (LPT scheduling for causal imbalance).
// grid: (S/128, B*H), 128 threads.
// ---------------------------------------------------------------------------
__global__ void __launch_bounds__(128) attn_mma_kernel()
{
    extern __shared__ __half smh[];
    __half* Qs = smh;              // 128*64
    __half* Ks = smh + 8192;       // 64*64
    __half* Vs = smh + 12288;      // 64*64  [d][key]
    __half* Ps = smh + 16384;      // 128*64
    const unsigned smb = (unsigned)__cvta_generic_to_shared(smh);
    const unsigned Qsb = smb;
    const unsigned Ksb = smb + 8192u*2;
    const unsigned Vsb = smb + 12288u*2;
    const unsigned Psb = smb + 16384u*2;

    const int bh = blockIdx.y;
    const int b  = bh / H;
    const int h  = bh % H;
    // LPT scheduling: highest-work tiles first
    const int qb = (S/128 - 1 - blockIdx.x) * 128;
    const int tid  = threadIdx.x;
    const int warp = tid >> 5;
    const int lane = tid & 31;
    const int grp  = lane >> 2;
    const int qr   = lane & 3;
    const int laneM = lane >> 3, laneR = lane & 7;
    const unsigned xr   = (unsigned)laneR << 3;
    const unsigned aw0  = (unsigned)(warp*32 + ((laneM&1)<<3) + laneR) * 64;
    const unsigned aw1  = aw0 + 1024;
    const unsigned acol = (unsigned)(laneM >> 1) << 3;
    const unsigned bw   = (unsigned)(((laneM>>1)<<3) + laneR) * 64;
    const unsigned bcol = (unsigned)(laneM & 1) << 3;

    const __half* kg  = g_k + (size_t)bh * S * 64;
    const __half* vgt = g_v + (size_t)bh * A * S;   // [d][s]
    const int j_start = (qb == S - 128) ? 0 : qb;
    const int nb = (S - j_start) >> 6;

    // ---- preload: {Q, K(0)} as one commit group, V(0) as the next ----
    const __half* qg = g_q + ((size_t)bh * S + qb) * 64;
    #pragma unroll
    for (int u = 0; u < 8; u++) {
        int idx = (u * 128 + tid) * 8;
        int r = idx >> 6, c = idx & 63;
        cpa16(&Qs[SWH(r, c)], &qg[idx]);
    }
    #pragma unroll
    for (int u = 0; u < 4; u++) {
        int idx = (u * 128 + tid) * 8;
        int r = idx >> 6, c = idx & 63;
        cpa16(&Ks[SWH(r, c)], &kg[(size_t)j_start * 64 + idx]);
    }
    CPA_COMMIT();                      // group: Q + K(0)
    #pragma unroll
    for (int u = 0; u < 4; u++) {
        int idx = (u * 128 + tid) * 8;
        int r = idx >> 6, c = idx & 63;
        cpa16(&Vs[SWH(r, c)], &vgt[(size_t)r * S + j_start + c]);
    }
    CPA_COMMIT();                      // group: V(0)

    float oacc[2][8][4];
    #pragma unroll
    for (int g = 0; g < 2; g++)
        #pragma unroll
        for (int nt = 0; nt < 8; nt++)
            #pragma unroll
            for (int j = 0; j < 4; j++) oacc[g][nt][j] = 0.0f;

    float m[4], l[4];
    #pragma unroll
    for (int q = 0; q < 4; q++) { m[q] = -INFINITY; l[q] = 0.0f; }

    for (int it = 0; it < nb; it++) {
        const int j0 = j_start + (it << 6);

        // ---- Q+K(it) arrived (V(it) may still be in flight) ----
        CPA_WAIT(1);
        __syncthreads();

        // ---- S = Q * K^T ----
        float sacc[2][8][4];
        #pragma unroll
        for (int g = 0; g < 2; g++)
            #pragma unroll
            for (int nt = 0; nt < 8; nt++)
                #pragma unroll
                for (int j = 0; j < 4; j++) sacc[g][nt][j] = 0.0f;

        #pragma unroll
        for (int ks = 0; ks < 4; ks++) {
            const unsigned K = ks * 16;
            unsigned qa0[4], qa1[4];
            ldsm4(qa0, Qsb + ((aw0 + ((K + acol) ^ xr)) << 1));
            ldsm4(qa1, Qsb + ((aw1 + ((K + acol) ^ xr)) << 1));
            #pragma unroll
            for (int np = 0; np < 4; np++) {
                unsigned kb[4];
                ldsm4(kb, Ksb + ((bw + np*1024u + ((K + bcol) ^ xr)) << 1));
                mma_f16(sacc[0][2*np],   qa0, kb[0], kb[1]);
                mma_f16(sacc[1][2*np],   qa1, kb[0], kb[1]);
                mma_f16(sacc[0][2*np+1], qa0, kb[2], kb[3]);
                mma_f16(sacc[1][2*np+1], qa1, kb[2], kb[3]);
            }
        }
        __syncthreads();   // all warps done reading Ks

        // ---- issue K(it+1) into Ks; overlaps softmax + PV ----
        if (it + 1 < nb) {
            int jn = j0 + 64;
            #pragma unroll
            for (int u = 0; u < 4; u++) {
                int idx = (u * 128 + tid) * 8;
                int r = idx >> 6, c = idx & 63;
                cpa16(&Ks[SWH(r, c)], &kg[(size_t)jn * 64 + idx]);
            }
            CPA_COMMIT();              // group: K(it+1)
        }

        // ---- mask + online softmax per row group; P -> Ps (fp16) ----
        #pragma unroll
        for (int g = 0; g < 2; g++) {
            const int iA = qb + warp * 32 + g * 16 + grp;
            const int iB = iA + 8;
            float tmaxA = -INFINITY, tmaxB = -INFINITY;
            #pragma unroll
            for (int nt = 0; nt < 8; nt++) {
                int j = j0 + nt*8 + 2*qr;
                if (j     <= iA) sacc[g][nt][0] = -1.0e9f;
                if (j + 1 <= iA) sacc[g][nt][1] = -1.0e9f;
                if (j     <= iB) sacc[g][nt][2] = -1.0e9f;
                if (j + 1 <= iB) sacc[g][nt][3] = -1.0e9f;
                tmaxA = fmaxf(tmaxA, fmaxf(sacc[g][nt][0], sacc[g][nt][1]));
                tmaxB = fmaxf(tmaxB, fmaxf(sacc[g][nt][2], sacc[g][nt][3]));
            }
            tmaxA = fmaxf(tmaxA, __shfl_xor_sync(0xffffffffu, tmaxA, 1));
            tmaxA = fmaxf(tmaxA, __shfl_xor_sync(0xffffffffu, tmaxA, 2));
            tmaxB = fmaxf(tmaxB, __shfl_xor_sync(0xffffffffu, tmaxB, 1));
            tmaxB = fmaxf(tmaxB, __shfl_xor_sync(0xffffffffu, tmaxB, 2));

            float mnA = fmaxf(m[2*g],   tmaxA);
            float mnB = fmaxf(m[2*g+1], tmaxB);
            float crA = __expf(m[2*g]   - mnA);   // first block: exp(-inf)=0
            float crB = __expf(m[2*g+1] - mnB);
            l[2*g]   *= crA; l[2*g+1] *= crB;
            m[2*g]    = mnA; m[2*g+1]  = mnB;
            #pragma unroll
            for (int nt = 0; nt < 8; nt++) {
                oacc[g][nt][0] *= crA; oacc[g][nt][1] *= crA;
                oacc[g][nt][2] *= crB; oacc[g][nt][3] *= crB;
            }

            float lsA = 0.0f, lsB = 0.0f;
            int rb = warp * 32 + g * 16 + grp;
            #pragma unroll
            for (int nt = 0; nt < 8; nt++) {
                float p0 = __expf(sacc[g][nt][0] - mnA);
                float p1 = __expf(sacc[g][nt][1] - mnA);
                float p2 = __expf(sacc[g][nt][2] - mnB);
                float p3 = __expf(sacc[g][nt][3] - mnB);
                lsA += p0 + p1; lsB += p2 + p3;
                int c = nt*8 + 2*qr;
                *(__half2*)&Ps[SWH(rb, c)]     = __floats2half2_rn(p0, p1);
                *(__half2*)&Ps[SWH(rb + 8, c)] = __floats2half2_rn(p2, p3);
            }
            l[2*g] += lsA; l[2*g+1] += lsB;
        }
        __syncwarp();   // P rows are warp-private; order stores before loads

        // ---- V(it) arrived (pending: K(it+1) if committed) ----
        if (it + 1 < nb) { CPA_WAIT(1); } else { CPA_WAIT(0); }
        __syncthreads();

        // ---- O += P * V ----
        #pragma unroll
        for (int ks = 0; ks < 4; ks++) {
            const unsigned K = ks * 16;
            unsigned pa0[4], pa1[4];
            ldsm4(pa0, Psb + ((aw0 + ((K + acol) ^ xr)) << 1));
            ldsm4(pa1, Psb + ((aw1 + ((K + acol) ^ xr)) << 1));
            #pragma unroll
            for (int np = 0; np < 4; np++) {
                unsigned vb[4];
                ldsm4(vb, Vsb + ((bw + np*1024u + ((K + bcol) ^ xr)) << 1));
                mma_f16(oacc[0][2*np],   pa0, vb[0], vb[1]);
                mma_f16(oacc[1][2*np],   pa1, vb[0], vb[1]);
                mma_f16(oacc[0][2*np+1], pa0, vb[2], vb[3]);
                mma_f16(oacc[1][2*np+1], pa1, vb[2], vb[3]);
            }
        }
        __syncthreads();   // all warps done reading Vs

        // ---- issue V(it+1) into Vs; overlaps next QK ----
        if (it + 1 < nb) {
            int jn = j0 + 64;
            #pragma unroll
            for (int u = 0; u < 4; u++) {
                int idx = (u * 128 + tid) * 8;
                int r = idx >> 6, c = idx & 63;
                cpa16(&Vs[SWH(r, c)], &vgt[(size_t)r * S + jn + c]);
            }
            CPA_COMMIT();              // group: V(it+1)
        }
    }

    // ---- quad-reduce softmax denominators ----
    #pragma unroll
    for (int q = 0; q < 4; q++) {
        l[q] += __shfl_xor_sync(0xffffffffu, l[q], 1);
        l[q] += __shfl_xor_sync(0xffffffffu, l[q], 2);
    }

    // ---- epilogue: normalize, fp16, head-concat layout ----
    #pragma unroll
    for (int g = 0; g < 2; g++) {
        const int iA = qb + warp * 32 + g * 16 + grp;
        const float invA = 1.0f / l[2*g];
        const float invB = 1.0f / l[2*g+1];
        __half* obA = g_attn + ((size_t)b * S + iA) * HA + h * A;
        __half* obB = g_attn + ((size_t)b * S + iA + 8) * HA + h * A;
        #pragma unroll
        for (int nt = 0; nt < 8; nt++) {
            int c = nt*8 + 2*qr;
            *(__half2*)&obA[c] = __floats2half2_rn(oacc[g][nt][0] * invA,
                                                   oacc[g][nt][1] * invA);
            *(__half2*)&obB[c] = __floats2half2_rn(oacc[g][nt][2] * invB,
                                                   oacc[g][nt][3] * invB);
        }
    }
}

// ---------------------------------------------------------------------------
// Kernel 3: output projection, fp16 mma. (R14, validated)
// ---------------------------------------------------------------------------
__global__ void __launch_bounds__(128) out_proj_f16_kernel(
    const float* __restrict__ bo, float* __restrict__ out)
{
    extern __shared__ __half smh[];
    __half* Xb[2] = { smh,          smh + 8192  };
    __half* Wb[2] = { smh + 16384,  smh + 20480 };
    const unsigned smb = (unsigned)__cvta_generic_to_shared(smh);
    const unsigned Xbb[2] = { smb,             smb + 8192u*2  };
    const unsigned Wbb[2] = { smb + 16384u*2,  smb + 20480u*2 };

    const int n0 = blockIdx.x * 64;
    const int s0 = blockIdx.y * 128;
    const int tid  = threadIdx.x;
    const int warp = tid >> 5;
    const int lane = tid & 31;
    const int grp  = lane >> 2;
    const int qr   = lane & 3;
    const int laneM = lane >> 3, laneR = lane & 7;
    const unsigned xr   = (unsigned)laneR << 3;
    const unsigned aw0  = (unsigned)(warp*32 + ((laneM&1)<<3) + laneR) * 64;
    const unsigned aw1  = aw0 + 1024;
    const unsigned acol = (unsigned)(laneM >> 1) << 3;
    const unsigned bw   = (unsigned)(((laneM>>1)<<3) + laneR) * 64;
    const unsigned bcol = (unsigned)(laneM & 1) << 3;

    float acc[2][8][4];
    #pragma unroll
    for (int g = 0; g < 2; g++)
        #pragma unroll
        for (int nt = 0; nt < 8; nt++)
            #pragma unroll
            for (int j = 0; j < 4; j++) acc[g][nt][j] = 0.0f;

    {
        #pragma unroll
        for (int u = 0; u < 8; u++) {
            int idx = (u * 128 + tid) * 8;
            int r = idx >> 6, c = idx & 63;
            cpa16(&Xb[0][SWH(r, c)], &g_attn[(size_t)(s0 + r) * HA + c]);
        }
        #pragma unroll
        for (int u = 0; u < 4; u++) {
            int idx = (u * 128 + tid) * 8;
            int r = idx >> 6, c = idx & 63;
            cpa16(&Wb[0][SWH(r, c)], &g_wo[(size_t)(n0 + r) * HA + c]);
        }
        CPA_COMMIT();
    }

    for (int ci = 0; ci < 8; ci++) {
        if (ci < 7) {
            int k0 = (ci + 1) * 64;
            __half* Xd = Xb[(ci + 1) & 1];
            __half* Wd = Wb[(ci + 1) & 1];
            #pragma unroll
            for (int u = 0; u < 8; u++) {
                int idx = (u * 128 + tid) * 8;
                int r = idx >> 6, c = idx & 63;
                cpa16(&Xd[SWH(r, c)], &g_attn[(size_t)(s0 + r) * HA + k0 + c]);
            }
            #pragma unroll
            for (int u = 0; u < 4; u++) {
                int idx = (u * 128 + tid) * 8;
                int r = idx >> 6, c = idx & 63;
                cpa16(&Wd[SWH(r, c)], &g_wo[(size_t)(n0 + r) * HA + k0 + c]);
            }
            CPA_COMMIT();
            CPA_WAIT(1);
        } else {
            CPA_WAIT(0);
        }
        __syncthreads();

        const unsigned Xs = Xbb[ci & 1];
        const unsigned Ws = Wbb[ci & 1];
        #pragma unroll
        for (int ks = 0; ks < 4; ks++) {
            const unsigned K = ks * 16;
            unsigned af0[4], af1[4];
            ldsm4(af0, Xs + ((aw0 + ((K + acol) ^ xr)) << 1));
            ldsm4(af1, Xs + ((aw1 + ((K + acol) ^ xr)) << 1));
            #pragma unroll
            for (int np = 0; np < 4; np++) {
                unsigned bf[4];
                ldsm4(bf, Ws + ((bw + np*1024u + ((K + bcol) ^ xr)) << 1));
                mma_f16(acc[0][2*np],   af0, bf[0], bf[1]);
                mma_f16(acc[1][2*np],   af1, bf[0], bf[1]);
                mma_f16(acc[0][2*np+1], af0, bf[2], bf[3]);
                mma_f16(acc[1][2*np+1], af1, bf[2], bf[3]);
            }
        }
        __syncthreads();
    }

    #pragma unroll
    for (int g = 0; g < 2; g++) {
        int rb = warp * 32 + g * 16 + grp;
        #pragma unroll
        for (int nt = 0; nt < 8; nt++) {
            int c = nt*8 + 2*qr;
            float2 bv2 = make_float2(bo[n0 + c], bo[n0 + c + 1]);
            *(float2*)&out[(size_t)(s0 + rb) * D + n0 + c] =
                make_float2(acc[g][nt][0] + bv2.x, acc[g][nt][1] + bv2.y);
            *(float2*)&out[(size_t)(s0 + rb + 8) * D + n0 + c] =
                make_float2(acc[g][nt][2] + bv2.x, acc[g][nt][3] + bv2.y);
        }
    }
}

// ---------------------------------------------------------------------------
extern "C" void kernel_launch(void* const* d_in, const int* in_sizes, int n_in,
                              void* d_out, int out_size)
{
    const float* query = (const float*)d_in[0];
    const float* key   = (const float*)d_in[1];
    const float* value = (const float*)d_in[2];
    const float* Wq    = (const float*)d_in[3];
    const float* bq    = (const float*)d_in[4];
    const float* Wk    = (const float*)d_in[5];
    const float* bk    = (const float*)d_in[6];
    const float* Wv    = (const float*)d_in[7];
    const float* bv    = (const float*)d_in[8];
    const float* Wo    = (const float*)d_in[9];
    const float* bo    = (const float*)d_in[10];
    float* out = (float*)d_out;

    (void)in_sizes; (void)n_in; (void)out_size;

    prep_kernel<<<NXB + 1024, 256>>>(query, key, value, Wq, Wk, Wv, Wo);

    // dynamic smem attribute sets: idempotent, capture-safe, no allocation
    static const int SMEM48 = 24576 * (int)sizeof(__half);   // 49152 B
    cudaFuncSetAttribute(proj_f16_kernel,
                         cudaFuncAttributeMaxDynamicSharedMemorySize, SMEM48);
    cudaFuncSetAttribute(attn_mma_kernel,
                         cudaFuncAttributeMaxDynamicSharedMemorySize, SMEM48);
    cudaFuncSetAttribute(out_proj_f16_kernel,
                         cudaFuncAttributeMaxDynamicSharedMemorySize, SMEM48);

    proj_f16_kernel<<<dim3(S / 128, 3 * B * H), 128, SMEM48>>>(bq, bk, bv);

    attn_mma_kernel<<<dim3(S / 128, B * H), 128, SMEM48>>>();

    out_proj_f16_kernel<<<dim3(D / 64, (B * S) / 128), 128, SMEM48>>>(bo, out);
}